// round 5
// baseline (speedup 1.0000x reference)
#include <cuda_runtime.h>
#include <cuda_bf16.h>
#include <cstdint>

#define NN 50000
#define NE 800000
#define AF 133
#define BF 14
#define H  128
#define SA_STRIDE 136   // padded bf16 smem row stride (272B -> conflict-free LDSM)
#define SD_STRIDE 132   // padded fp32 smem row stride for epilogue
#define MATB (128 * SA_STRIDE)          // bf16 elems per smem matrix (34816 B)
#define TILES_PER_CTA 5
#define EGRID (NE / 128 / TILES_PER_CTA)   // 1250

// ---------------- scratch (device globals; no allocation) ----------------
__device__ __nv_bfloat16 g_hh[(size_t)NE * H];   // edge hidden, bf16 hi
__device__ __nv_bfloat16 g_hl[(size_t)NE * H];   // edge hidden, bf16 lo
__device__ float g_y1[(size_t)NE * H];           // Y1 = h0 @ Wh^T
__device__ float g_y2[(size_t)NE * H];           // Y2 = h1 @ Wh^T
__device__ float g_P [(size_t)NN * H];           // atom @ Wa^T
__device__ float g_S1[(size_t)NN * H];
__device__ float g_S2[(size_t)NN * H];
__device__ float g_S3[(size_t)NN * H];
// transposed weights for SIMT node GEMMs: WaT[133x128] | WbT[14x128] | pad | WoT[261x128]
__device__ float g_WT[(size_t)(AF + BF + H + (AF + H)) * H];
// Wh split to bf16 hi/lo, plain row-major [n][k]
__device__ __nv_bfloat16 g_Bh[H * H];
__device__ __nv_bfloat16 g_Bl[H * H];
__device__ int   g_idx64;

// ---------------- helpers ----------------
__device__ __forceinline__ int ld_idx(const void* p, long i) {
    if (g_idx64) return (int)__ldg((const long long*)p + i);
    return __ldg((const int*)p + i);
}
__device__ __forceinline__ void red4(float* p, float4 v) {
    asm volatile("red.global.add.v4.f32 [%0], {%1,%2,%3,%4};"
                 :: "l"(p), "f"(v.x), "f"(v.y), "f"(v.z), "f"(v.w) : "memory");
}
__device__ __forceinline__ uint32_t smem_u32(const void* p) {
    uint32_t a;
    asm("{ .reg .u64 t; cvta.to.shared.u64 t, %1; cvt.u32.u64 %0, t; }" : "=r"(a) : "l"(p));
    return a;
}
__device__ __forceinline__ void cp_async16(uint32_t sdst, const void* gsrc) {
    asm volatile("cp.async.cg.shared.global [%0], [%1], 16;" :: "r"(sdst), "l"(gsrc) : "memory");
}
__device__ __forceinline__ void cp_commit() {
    asm volatile("cp.async.commit_group;" ::: "memory");
}
template<int N> __device__ __forceinline__ void cp_wait() {
    asm volatile("cp.async.wait_group %0;" :: "n"(N) : "memory");
}
__device__ __forceinline__ void bsplit(float v, __nv_bfloat16& h, __nv_bfloat16& l) {
    h = __float2bfloat16(v);
    l = __float2bfloat16(v - __bfloat162float(h));
}
__device__ __forceinline__ uint32_t bpack(__nv_bfloat16 a, __nv_bfloat16 b) {
    return ((uint32_t)__bfloat16_as_ushort(b) << 16) | (uint32_t)__bfloat16_as_ushort(a);
}
__device__ __forceinline__ void ldsm_x4(uint32_t (&r)[4], uint32_t addr) {
    asm volatile("ldmatrix.sync.aligned.m8n8.x4.shared.b16 {%0,%1,%2,%3}, [%4];"
                 : "=r"(r[0]), "=r"(r[1]), "=r"(r[2]), "=r"(r[3]) : "r"(addr));
}
__device__ __forceinline__ void ldsm_x2(uint32_t (&r)[2], uint32_t addr) {
    asm volatile("ldmatrix.sync.aligned.m8n8.x2.shared.b16 {%0,%1}, [%2];"
                 : "=r"(r[0]), "=r"(r[1]) : "r"(addr));
}
__device__ __forceinline__ void mma_bf16(float (&d)[4], const uint32_t (&a)[4], const uint32_t (&b)[2]) {
    asm volatile("mma.sync.aligned.m16n8k16.row.col.f32.bf16.bf16.f32 "
                 "{%0,%1,%2,%3}, {%4,%5,%6,%7}, {%8,%9}, {%0,%1,%2,%3};"
                 : "+f"(d[0]), "+f"(d[1]), "+f"(d[2]), "+f"(d[3])
                 : "r"(a[0]), "r"(a[1]), "r"(a[2]), "r"(a[3]), "r"(b[0]), "r"(b[1]));
}

// ---------------- detect int32 vs int64 index arrays ----------------
__global__ void detect_idx(const unsigned int* srcw) {
    __shared__ unsigned int s;
    if (threadIdx.x == 0) s = 0;
    __syncthreads();
    unsigned int v = srcw[threadIdx.x * 2 + 1] | srcw[2048 + threadIdx.x * 2 + 1];
    atomicOr(&s, v);
    __syncthreads();
    if (threadIdx.x == 0) g_idx64 = (s == 0u) ? 1 : 0;
}

// ---------------- weight prep ----------------
__global__ void prep_w(const float* __restrict__ Wi, const float* __restrict__ Wh,
                       const float* __restrict__ Wo) {
    int i = blockIdx.x * blockDim.x + threadIdx.x;
    if (i >= (AF + H) * H) return;
    int j = i & 127, k = i >> 7;
    if (k < AF) g_WT[i]          = Wi[j * (AF + BF) + k];                 // WaT
    if (k < BF) g_WT[AF * H + i] = Wi[j * (AF + BF) + AF + k];            // WbT
    if (k < AF + H) g_WT[(AF + BF + H) * H + i] = Wo[j * (AF + H) + k];   // WoT
    if (i < H * H) {
        __nv_bfloat16 hi, lo; bsplit(Wh[i], hi, lo);
        g_Bh[i] = hi;
        g_Bl[i] = lo;
    }
}

// ---------------- zero S1,S2,S3 in one kernel ----------------
__global__ void zero3(float4* a, float4* b, float4* c) {
    const long n = (long)NN * H / 4;
    long i = (long)blockIdx.x * blockDim.x + threadIdx.x;
    float4 z = make_float4(0.f, 0.f, 0.f, 0.f);
    if (i < n) a[i] = z;
    else if (i < 2 * n) b[i - n] = z;
    else c[i - 2 * n] = z;
}

// ---------------- node GEMM (SIMT fp32): out[N,H] = [A0|A1] @ sW ------------
template<int KD, bool RELU>
__global__ __launch_bounds__(256) void node_gemm(const float* __restrict__ A0,
                                                 const float* __restrict__ A1,
                                                 const float* __restrict__ WT,
                                                 float* __restrict__ out) {
    extern __shared__ float sm[];
    float* sW = sm;
    float* sA = sm + KD * H;
    for (int i = threadIdx.x; i < KD * H; i += 256) sW[i] = WT[i];
    __syncthreads();
    int warp = threadIdx.x >> 5, lane = threadIdx.x & 31;
    for (int base = blockIdx.x * 8; base < NN; base += gridDim.x * 8) {
        for (int i = threadIdx.x; i < 8 * KD; i += 256) {
            int r = i / KD, c = i % KD;
            float v = (c < AF) ? A0[(size_t)(base + r) * AF + c]
                               : A1[(size_t)(base + r) * H + (c - AF)];
            sA[r * KD + c] = v;
        }
        __syncthreads();
        const float* ar = sA + warp * KD;
        float4 acc = make_float4(0.f, 0.f, 0.f, 0.f);
        #pragma unroll 4
        for (int k = 0; k < KD; k++) {
            float a = ar[k];
            float4 w = *(const float4*)(sW + k * H + lane * 4);
            acc.x += a * w.x; acc.y += a * w.y; acc.z += a * w.z; acc.w += a * w.w;
        }
        if (RELU) {
            acc.x = fmaxf(acc.x, 0.f); acc.y = fmaxf(acc.y, 0.f);
            acc.z = fmaxf(acc.z, 0.f); acc.w = fmaxf(acc.w, 0.f);
        }
        *(float4*)(out + (size_t)(base + warp) * H + lane * 4) = acc;
        __syncthreads();
    }
}

// ---- initial edge layer: h0 = relu(P[src] + bond @ WbT), stored bf16 hi/lo -
__global__ __launch_bounds__(256) void init_edges(const float* __restrict__ bond,
                                                  const void* __restrict__ src) {
    __shared__ float sWb[BF * H];
    for (int i = threadIdx.x; i < BF * H; i += 256) sWb[i] = g_WT[AF * H + i];
    __syncthreads();
    int warp = threadIdx.x >> 5, lane = threadIdx.x & 31;
    for (long e0 = (long)blockIdx.x * 8; e0 < NE; e0 += (long)gridDim.x * 8) {
        long e = e0 + warp;
        int s = ld_idx(src, e);
        int q = lane * 4;
        float4 acc = *(const float4*)(g_P + (size_t)s * H + q);
        const float* br = bond + e * BF;
        #pragma unroll
        for (int k = 0; k < BF; k++) {
            float b = __ldg(br + k);
            float4 w = *(const float4*)(sWb + k * H + q);
            acc.x += b * w.x; acc.y += b * w.y; acc.z += b * w.z; acc.w += b * w.w;
        }
        acc.x = fmaxf(acc.x, 0.f); acc.y = fmaxf(acc.y, 0.f);
        acc.z = fmaxf(acc.z, 0.f); acc.w = fmaxf(acc.w, 0.f);
        __nv_bfloat16 h0,h1,h2,h3,l0,l1,l2,l3;
        bsplit(acc.x,h0,l0); bsplit(acc.y,h1,l1); bsplit(acc.z,h2,l2); bsplit(acc.w,h3,l3);
        size_t off = (size_t)e * H + q;
        *(uint2*)(g_hh + off) = make_uint2(bpack(h0,h1), bpack(h2,h3));
        *(uint2*)(g_hl + off) = make_uint2(bpack(l0,l1), bpack(l2,l3));
    }
}

// ---------------- persistent tensor-core edge GEMM --------------------------
// Each CTA: TILES_PER_CTA tiles of 128 edges. B (hi/lo) resident in smem.
// MODE 0: A prefetched from g_hh/g_hl via cp.async double-buffer
//         (issue t+1 prefetch FIRST, then wait_group 1 to drain tile t).
// MODE 1: A = relu(Sprev[src]-Yprev[rev]) built in registers per tile.
// Epilogue: D staged via smem (reuses the retired A stage) -> coalesced Y write
//           + red.add.v4 scatter into Sout[dst].
template<int MODE>
__global__ __launch_bounds__(512, 1) void egemm2(
    const __nv_bfloat16* __restrict__ Ah, const __nv_bfloat16* __restrict__ Al,
    const float* __restrict__ Sprev, const float* __restrict__ Yprev,
    const void* __restrict__ srcp, const void* __restrict__ revp,
    const uint4* __restrict__ Bh4, const uint4* __restrict__ Bl4,
    float* __restrict__ Yout, float* __restrict__ Sout,
    const void* __restrict__ dstp)
{
    extern __shared__ __align__(16) char dyn[];
    __nv_bfloat16* sBh = (__nv_bfloat16*)dyn;
    __nv_bfloat16* sBl = sBh + MATB;
    __nv_bfloat16* sSt0 = sBl + MATB;                    // stage 0: Ah|Al
    __nv_bfloat16* sSt1 = sSt0 + 2 * MATB;               // stage 1 (MODE 0 only)

    int tid = threadIdx.x, lane = tid & 31, wid = tid >> 5;

    // ---- B (hi/lo) into padded smem (once per CTA)
    #pragma unroll
    for (int it = 0; it < 4; it++) {
        int i = tid + it * 512;                 // 2048 x 16B per matrix
        int r = i >> 4, c = i & 15;
        *(uint4*)(sBh + r * SA_STRIDE + c * 8) = __ldg(Bh4 + i);
        *(uint4*)(sBl + r * SA_STRIDE + c * 8) = __ldg(Bl4 + i);
    }

    long tile0 = (long)blockIdx.x * TILES_PER_CTA;

    // MODE 0: prefetch A tile 0 into stage 0
    if (MODE == 0) {
        uint32_t st = smem_u32(sSt0);
        long e0 = tile0 * 128;
        #pragma unroll
        for (int it = 0; it < 4; it++) {
            int i = tid + it * 512;
            int r = i >> 4, c = i & 15;
            uint32_t doff = (uint32_t)(r * SA_STRIDE + c * 8) * 2;
            cp_async16(st + doff, Ah + (size_t)(e0 + r) * H + c * 8);
            cp_async16(st + (uint32_t)MATB * 2 + doff, Al + (size_t)(e0 + r) * H + c * 8);
        }
        cp_commit();
    }

    int wm = (wid >> 2) * 32;
    int wn = (wid & 3) * 32;

    for (int t = 0; t < TILES_PER_CTA; t++) {
        long e0 = (tile0 + t) * 128;
        __nv_bfloat16* sA = (MODE == 0) ? ((t & 1) ? sSt1 : sSt0) : sSt0;
        __nv_bfloat16* sAh = sA;
        __nv_bfloat16* sAl = sA + MATB;

        if (MODE == 0) {
            // FIRST issue prefetch of tile t+1 into the other stage, THEN drain
            // tile t's group (wait_group 1 leaves only t+1's group in flight).
            if (t + 1 < TILES_PER_CTA) {
                __nv_bfloat16* nx = (t & 1) ? sSt0 : sSt1;
                uint32_t st = smem_u32(nx);
                long en = (tile0 + t + 1) * 128;
                #pragma unroll
                for (int it = 0; it < 4; it++) {
                    int i = tid + it * 512;
                    int r = i >> 4, c = i & 15;
                    uint32_t doff = (uint32_t)(r * SA_STRIDE + c * 8) * 2;
                    cp_async16(st + doff, Ah + (size_t)(en + r) * H + c * 8);
                    cp_async16(st + (uint32_t)MATB * 2 + doff, Al + (size_t)(en + r) * H + c * 8);
                }
                cp_commit();
                cp_wait<1>();
            } else {
                cp_wait<0>();
            }
            __syncthreads();
        } else {
            // build A = relu(S[src] - Y[rev]), split hi/lo
            int row = tid >> 2, q = tid & 3;
            long e = e0 + row;
            int  s = ld_idx(srcp, e);
            long r = ld_idx(revp, e);
            const float4* ps = (const float4*)(Sprev + (size_t)s * H + q * 32);
            const float4* py = (const float4*)(Yprev + (size_t)r * H + q * 32);
            uint2* dh = (uint2*)(sAh + row * SA_STRIDE + q * 32);
            uint2* dl = (uint2*)(sAl + row * SA_STRIDE + q * 32);
            #pragma unroll
            for (int i = 0; i < 8; i++) {
                float4 sv = __ldg(ps + i), yv = __ldg(py + i);
                float4 hv;
                hv.x = fmaxf(sv.x - yv.x, 0.f); hv.y = fmaxf(sv.y - yv.y, 0.f);
                hv.z = fmaxf(sv.z - yv.z, 0.f); hv.w = fmaxf(sv.w - yv.w, 0.f);
                __nv_bfloat16 h0,h1,h2,h3,l0,l1,l2,l3;
                bsplit(hv.x,h0,l0); bsplit(hv.y,h1,l1); bsplit(hv.z,h2,l2); bsplit(hv.w,h3,l3);
                dh[i] = make_uint2(bpack(h0,h1), bpack(h2,h3));
                dl[i] = make_uint2(bpack(l0,l1), bpack(l2,l3));
            }
            __syncthreads();
        }

        // ---- mainloop: 3 passes x 8 ksteps; warp grid 4x4, warp tile 32x32
        float acc[2][4][4];
        #pragma unroll
        for (int mt = 0; mt < 2; mt++)
            #pragma unroll
            for (int nt = 0; nt < 4; nt++)
                #pragma unroll
                for (int i = 0; i < 4; i++) acc[mt][nt][i] = 0.f;

        #pragma unroll
        for (int pass = 0; pass < 3; pass++) {
            uint32_t abase = smem_u32(pass == 1 ? sAl : sAh);
            uint32_t bbase = smem_u32(pass == 2 ? sBl : sBh);
            uint32_t aAddr0 = abase + ((uint32_t)(wm + (lane & 15)) * SA_STRIDE + (lane >> 4) * 8) * 2;
            uint32_t aAddr1 = aAddr0 + 16 * SA_STRIDE * 2;
            uint32_t bAddr  = bbase + ((uint32_t)(wn + (lane & 7)) * SA_STRIDE + ((lane >> 3) & 1) * 8) * 2;
            #pragma unroll
            for (int ks = 0; ks < 8; ks++) {
                uint32_t koff = (uint32_t)ks * 32;
                uint32_t a0[4], a1[4];
                ldsm_x4(a0, aAddr0 + koff);
                ldsm_x4(a1, aAddr1 + koff);
                uint32_t b[4][2];
                #pragma unroll
                for (int nt = 0; nt < 4; nt++)
                    ldsm_x2(b[nt], bAddr + (uint32_t)nt * 8 * SA_STRIDE * 2 + koff);
                #pragma unroll
                for (int nt = 0; nt < 4; nt++) {
                    mma_bf16(acc[0][nt], a0, b[nt]);
                    mma_bf16(acc[1][nt], a1, b[nt]);
                }
            }
        }
        __syncthreads();            // all warps done reading sA

        // ---- D fragments -> smem fp32 tile (overlays this tile's A stage)
        float* sD = (float*)sA;
        {
            int g = lane >> 2, t2 = (lane & 3) * 2;
            #pragma unroll
            for (int mt = 0; mt < 2; mt++)
                #pragma unroll
                for (int nt = 0; nt < 4; nt++) {
                    int r0 = wm + mt * 16 + g, c0 = wn + nt * 8 + t2;
                    *(float2*)(sD + r0 * SD_STRIDE + c0)       = make_float2(acc[mt][nt][0], acc[mt][nt][1]);
                    *(float2*)(sD + (r0 + 8) * SD_STRIDE + c0) = make_float2(acc[mt][nt][2], acc[mt][nt][3]);
                }
        }
        __syncthreads();

        // ---- epilogue: thread t: row t&127, 32-col chunk t>>7
        {
            int row = tid & 127, q = tid >> 7;
            long e = e0 + row;
            int d = ld_idx(dstp, e);
            const float4* sp = (const float4*)(sD + row * SD_STRIDE + q * 32);
            float* yrow = Yout + (size_t)e * H + q * 32;
            float* srow = Sout + (size_t)d * H + q * 32;
            #pragma unroll
            for (int i = 0; i < 8; i++) {
                float4 v = sp[i];
                *(float4*)(yrow + i * 4) = v;
                red4(srow + i * 4, v);
            }
        }
        __syncthreads();            // stage free for reuse (prefetch/build/D)
    }
}

// ------- final combine: scatter relu(S2[src] - Y2[rev]) into S3[dst] --------
__global__ __launch_bounds__(256) void combine2(const float* __restrict__ S,
                                                const float* __restrict__ Yv,
                                                const void* __restrict__ src,
                                                const void* __restrict__ rev,
                                                float* __restrict__ S3,
                                                const void* __restrict__ dst) {
    long g = (long)blockIdx.x * 256 + threadIdx.x;
    long e = g >> 5;
    if (e >= NE) return;
    int q = (int)(g & 31) * 4;
    int s = ld_idx(src, e);
    long r = ld_idx(rev, e);
    int d = ld_idx(dst, e);
    float4 sv = *(const float4*)(S + (size_t)s * H + q);
    float4 yv = *(const float4*)(Yv + (size_t)r * H + q);
    float4 h;
    h.x = fmaxf(sv.x - yv.x, 0.f);
    h.y = fmaxf(sv.y - yv.y, 0.f);
    h.z = fmaxf(sv.z - yv.z, 0.f);
    h.w = fmaxf(sv.w - yv.w, 0.f);
    red4(S3 + (size_t)d * H + q, h);
}

// ---------------- launcher ----------------
extern "C" void kernel_launch(void* const* d_in, const int* in_sizes, int n_in,
                              void* d_out, int out_size) {
    const float* atom = (const float*)d_in[0];
    const float* bond = (const float*)d_in[1];
    const float* Wi   = (const float*)d_in[2];
    const float* Wh   = (const float*)d_in[3];
    const float* Wo   = (const float*)d_in[4];
    const void*  src  = d_in[5];
    const void*  dst  = d_in[6];
    const void*  rev  = d_in[7];
    float* out = (float*)d_out;

    __nv_bfloat16 *hh, *hl, *Bh, *Bl;
    float *y1, *y2, *P, *S1, *S2, *S3, *WT;
    cudaGetSymbolAddress((void**)&hh, g_hh);
    cudaGetSymbolAddress((void**)&hl, g_hl);
    cudaGetSymbolAddress((void**)&Bh, g_Bh);
    cudaGetSymbolAddress((void**)&Bl, g_Bl);
    cudaGetSymbolAddress((void**)&y1, g_y1);
    cudaGetSymbolAddress((void**)&y2, g_y2);
    cudaGetSymbolAddress((void**)&P,  g_P);
    cudaGetSymbolAddress((void**)&S1, g_S1);
    cudaGetSymbolAddress((void**)&S2, g_S2);
    cudaGetSymbolAddress((void**)&S3, g_S3);
    cudaGetSymbolAddress((void**)&WT, g_WT);
    const float* WoT = WT + (AF + BF + H) * H;

    const int smemP = (AF * H + 8 * AF) * 4;
    const int smemO = ((AF + H) * H + 8 * (AF + H)) * 4;
    const int smemG0 = 6 * MATB * 2;   // B(2) + 2 stages(2 each) = 208896 B
    const int smemG1 = 4 * MATB * 2;   // B(2) + 1 stage(2)      = 139264 B
    cudaFuncSetAttribute(node_gemm<AF, false>,    cudaFuncAttributeMaxDynamicSharedMemorySize, smemP);
    cudaFuncSetAttribute(node_gemm<AF + H, true>, cudaFuncAttributeMaxDynamicSharedMemorySize, smemO);
    cudaFuncSetAttribute(egemm2<0>, cudaFuncAttributeMaxDynamicSharedMemorySize, smemG0);
    cudaFuncSetAttribute(egemm2<1>, cudaFuncAttributeMaxDynamicSharedMemorySize, smemG1);

    detect_idx<<<1, 256>>>((const unsigned int*)src);
    prep_w<<<((AF + H) * H + 255) / 256, 256>>>(Wi, Wh, Wo);
    zero3<<<3 * NN * H / 4 / 256, 256>>>((float4*)S1, (float4*)S2, (float4*)S3);

    // P = atom @ Wa^T
    node_gemm<AF, false><<<296, 256, smemP>>>(atom, nullptr, WT, P);
    // h0 (bf16 hi/lo) = relu(P[src] + bond @ Wb^T)
    init_edges<<<2048, 256>>>(bond, src);

    // iter 1: Y1 = h0 @ Wh^T (persistent, cp.async double-buffered), scatter S1
    egemm2<0><<<EGRID, 512, smemG0>>>(hh, hl, nullptr, nullptr, nullptr, nullptr,
                                      (const uint4*)Bh, (const uint4*)Bl, y1, S1, dst);
    // iter 2: rows = relu(S1[src] - Y1[rev]) built in prologue; Y2, scatter S2
    egemm2<1><<<EGRID, 512, smemG1>>>(nullptr, nullptr, S1, y1, src, rev,
                                      (const uint4*)Bh, (const uint4*)Bl, y2, S2, dst);
    // final combine: scatter relu(S2[src] - Y2[rev]) into S3
    combine2<<<NE * 32 / 256, 256>>>(S2, y2, src, rev, S3, dst);

    // out = relu([atom | S3] @ Wo^T)
    node_gemm<AF + H, true><<<296, 256, smemO>>>(atom, S3, WoT, out);
}

// round 6
// speedup vs baseline: 1.1543x; 1.1543x over previous
#include <cuda_runtime.h>
#include <cuda_bf16.h>
#include <cstdint>

#define NN 50000
#define NE 800000
#define AF 133
#define BF 14
#define H  128
#define SA_STRIDE 136   // padded bf16 smem row stride for egemm tiles
#define SD_STRIDE 132   // padded fp32 smem row stride for epilogues
#define MATB (128 * SA_STRIDE)
#define TILES_PER_CTA 5
#define EGRID (NE / 128 / TILES_PER_CTA)   // 1250

// node-gemm tiling: K chunks of 144, smem row stride 152 (304B: 48B rotation)
#define NGS  152
#define NGMAT (128 * NGS)
#define NROWS_PAD 50048            // 391 * 128
#define NGRID 391

// ---------------- scratch (device globals; no allocation) ----------------
__device__ __nv_bfloat16 g_hh[(size_t)NE * H];
__device__ __nv_bfloat16 g_hl[(size_t)NE * H];
__device__ float g_y1[(size_t)NE * H];
__device__ float g_y2[(size_t)NE * H];
__device__ float g_P [(size_t)NN * H];
__device__ float g_S1[(size_t)NN * H];
__device__ float g_S2[(size_t)NN * H];
__device__ float g_S3[(size_t)NN * H];
__device__ float g_WbT[BF * H];                    // WbT for init_edges
__device__ __nv_bfloat16 g_Bh[H * H];              // Wh hi  [n][k]
__device__ __nv_bfloat16 g_Bl[H * H];              // Wh lo
__device__ __nv_bfloat16 g_W1h[128 * 144];         // Wa padded, hi  [n][k]
__device__ __nv_bfloat16 g_W1l[128 * 144];
__device__ __nv_bfloat16 g_W2h[128 * 288];         // Wo padded, hi  [n][k]
__device__ __nv_bfloat16 g_W2l[128 * 288];
__device__ __nv_bfloat16 g_A1h[(size_t)NROWS_PAD * 144];   // atom panel hi
__device__ __nv_bfloat16 g_A1l[(size_t)NROWS_PAD * 144];
__device__ __nv_bfloat16 g_A2h[(size_t)NROWS_PAD * 288];   // [atom|S3] panel hi
__device__ __nv_bfloat16 g_A2l[(size_t)NROWS_PAD * 288];
__device__ int   g_idx64;

// ---------------- helpers ----------------
__device__ __forceinline__ int ld_idx(const void* p, long i) {
    if (g_idx64) return (int)__ldg((const long long*)p + i);
    return __ldg((const int*)p + i);
}
__device__ __forceinline__ void red4(float* p, float4 v) {
    asm volatile("red.global.add.v4.f32 [%0], {%1,%2,%3,%4};"
                 :: "l"(p), "f"(v.x), "f"(v.y), "f"(v.z), "f"(v.w) : "memory");
}
__device__ __forceinline__ uint32_t smem_u32(const void* p) {
    uint32_t a;
    asm("{ .reg .u64 t; cvta.to.shared.u64 t, %1; cvt.u32.u64 %0, t; }" : "=r"(a) : "l"(p));
    return a;
}
__device__ __forceinline__ void cp_async16(uint32_t sdst, const void* gsrc) {
    asm volatile("cp.async.cg.shared.global [%0], [%1], 16;" :: "r"(sdst), "l"(gsrc) : "memory");
}
__device__ __forceinline__ void cp_commit() {
    asm volatile("cp.async.commit_group;" ::: "memory");
}
template<int N> __device__ __forceinline__ void cp_wait() {
    asm volatile("cp.async.wait_group %0;" :: "n"(N) : "memory");
}
__device__ __forceinline__ void bsplit(float v, __nv_bfloat16& h, __nv_bfloat16& l) {
    h = __float2bfloat16(v);
    l = __float2bfloat16(v - __bfloat162float(h));
}
__device__ __forceinline__ uint32_t bpack(__nv_bfloat16 a, __nv_bfloat16 b) {
    return ((uint32_t)__bfloat16_as_ushort(b) << 16) | (uint32_t)__bfloat16_as_ushort(a);
}
__device__ __forceinline__ void ldsm_x4(uint32_t (&r)[4], uint32_t addr) {
    asm volatile("ldmatrix.sync.aligned.m8n8.x4.shared.b16 {%0,%1,%2,%3}, [%4];"
                 : "=r"(r[0]), "=r"(r[1]), "=r"(r[2]), "=r"(r[3]) : "r"(addr));
}
__device__ __forceinline__ void ldsm_x2(uint32_t (&r)[2], uint32_t addr) {
    asm volatile("ldmatrix.sync.aligned.m8n8.x2.shared.b16 {%0,%1}, [%2];"
                 : "=r"(r[0]), "=r"(r[1]) : "r"(addr));
}
__device__ __forceinline__ void mma_bf16(float (&d)[4], const uint32_t (&a)[4], const uint32_t (&b)[2]) {
    asm volatile("mma.sync.aligned.m16n8k16.row.col.f32.bf16.bf16.f32 "
                 "{%0,%1,%2,%3}, {%4,%5,%6,%7}, {%8,%9}, {%0,%1,%2,%3};"
                 : "+f"(d[0]), "+f"(d[1]), "+f"(d[2]), "+f"(d[3])
                 : "r"(a[0]), "r"(a[1]), "r"(a[2]), "r"(a[3]), "r"(b[0]), "r"(b[1]));
}

// ---------------- detect int32 vs int64 index arrays ----------------
__global__ void detect_idx(const unsigned int* srcw) {
    __shared__ unsigned int s;
    if (threadIdx.x == 0) s = 0;
    __syncthreads();
    unsigned int v = srcw[threadIdx.x * 2 + 1] | srcw[2048 + threadIdx.x * 2 + 1];
    atomicOr(&s, v);
    __syncthreads();
    if (threadIdx.x == 0) g_idx64 = (s == 0u) ? 1 : 0;
}

// ---------------- weight prep: all weights to bf16 hi/lo [n][k] -------------
__global__ void prep_w(const float* __restrict__ Wi, const float* __restrict__ Wh,
                       const float* __restrict__ Wo) {
    int i = blockIdx.x * blockDim.x + threadIdx.x;
    if (i >= 128 * 288) return;
    if (i < BF * H) {                    // WbT[k][j] = Wi[j][AF+k]  (fp32, init_edges)
        int j = i & 127, k = i >> 7;
        g_WbT[i] = Wi[j * (AF + BF) + AF + k];
    }
    if (i < H * H) {                     // Wh split, row-major [n][k]
        __nv_bfloat16 hi, lo; bsplit(Wh[i], hi, lo);
        g_Bh[i] = hi; g_Bl[i] = lo;
    }
    if (i < 128 * 144) {                 // W1: Wa part of Wi, K padded to 144
        int n = i / 144, k = i % 144;
        float v = (k < AF) ? Wi[n * (AF + BF) + k] : 0.f;
        __nv_bfloat16 hi, lo; bsplit(v, hi, lo);
        g_W1h[i] = hi; g_W1l[i] = lo;
    }
    {                                    // W2: Wo, K padded to 288
        int n = i / 288, k = i % 288;
        float v = (k < AF + H) ? Wo[n * (AF + H) + k] : 0.f;
        __nv_bfloat16 hi, lo; bsplit(v, hi, lo);
        g_W2h[i] = hi; g_W2l[i] = lo;
    }
}

// ---------------- zero S1,S2,S3 ----------------
__global__ void zero3(float4* a, float4* b, float4* c) {
    const long n = (long)NN * H / 4;
    long i = (long)blockIdx.x * blockDim.x + threadIdx.x;
    float4 z = make_float4(0.f, 0.f, 0.f, 0.f);
    if (i < n) a[i] = z;
    else if (i < 2 * n) b[i - n] = z;
    else c[i - 2 * n] = z;
}

// ---------------- A-panel conversions (zero-padded bf16 hi/lo) --------------
__global__ void cvt1(const float* __restrict__ atom) {
    long i = (long)blockIdx.x * blockDim.x + threadIdx.x;
    if (i >= (long)NROWS_PAD * 144) return;
    int r = (int)(i / 144), c = (int)(i % 144);
    float v = (r < NN && c < AF) ? __ldg(atom + (size_t)r * AF + c) : 0.f;
    __nv_bfloat16 hi, lo; bsplit(v, hi, lo);
    g_A1h[i] = hi; g_A1l[i] = lo;
}
__global__ void cvt2(const float* __restrict__ atom, const float* __restrict__ S3) {
    long i = (long)blockIdx.x * blockDim.x + threadIdx.x;
    if (i >= (long)NROWS_PAD * 288) return;
    int r = (int)(i / 288), c = (int)(i % 288);
    float v = 0.f;
    if (r < NN) {
        if (c < AF) v = __ldg(atom + (size_t)r * AF + c);
        else if (c < AF + H) v = __ldg(S3 + (size_t)r * H + (c - AF));
    }
    __nv_bfloat16 hi, lo; bsplit(v, hi, lo);
    g_A2h[i] = hi; g_A2l[i] = lo;
}

// ---------------- node GEMM via mma.sync (bf16 hi/lo 3-pass) -----------------
// out[128-row tile][128] = A @ W^T; K in chunks of 144; optional relu; row guard.
template<int KPAD, bool RELU>
__global__ __launch_bounds__(512, 1) void ngemm(
    const __nv_bfloat16* __restrict__ Ahg, const __nv_bfloat16* __restrict__ Alg,
    const __nv_bfloat16* __restrict__ Whg, const __nv_bfloat16* __restrict__ Wlg,
    float* __restrict__ out)
{
    extern __shared__ __align__(16) char dyn[];
    __nv_bfloat16* sBh = (__nv_bfloat16*)dyn;
    __nv_bfloat16* sBl = sBh + NGMAT;
    __nv_bfloat16* sAh = sBl + NGMAT;
    __nv_bfloat16* sAl = sAh + NGMAT;

    int tid = threadIdx.x, lane = tid & 31, wid = tid >> 5;
    int m0 = blockIdx.x * 128;
    int wm = (wid >> 2) * 32, wn = (wid & 3) * 32;

    float acc[2][4][4];
    #pragma unroll
    for (int mt = 0; mt < 2; mt++)
        #pragma unroll
        for (int nt = 0; nt < 4; nt++)
            #pragma unroll
            for (int i = 0; i < 4; i++) acc[mt][nt][i] = 0.f;

    const int NCH = KPAD / 144;
    #pragma unroll
    for (int ch = 0; ch < NCH; ch++) {
        if (ch) __syncthreads();
        for (int i = tid; i < 128 * 18; i += 512) {
            int r = i / 18, c = i % 18;
            int go = r * KPAD + ch * 144 + c * 8;
            *(uint4*)(sBh + r * NGS + c * 8) = *(const uint4*)(Whg + go);
            *(uint4*)(sBl + r * NGS + c * 8) = *(const uint4*)(Wlg + go);
        }
        for (int i = tid; i < 128 * 18; i += 512) {
            int r = i / 18, c = i % 18;
            size_t go = (size_t)(m0 + r) * KPAD + ch * 144 + c * 8;
            *(uint4*)(sAh + r * NGS + c * 8) = *(const uint4*)(Ahg + go);
            *(uint4*)(sAl + r * NGS + c * 8) = *(const uint4*)(Alg + go);
        }
        __syncthreads();

        #pragma unroll
        for (int pass = 0; pass < 3; pass++) {
            uint32_t abase = smem_u32(pass == 1 ? sAl : sAh);
            uint32_t bbase = smem_u32(pass == 2 ? sBl : sBh);
            uint32_t aAddr0 = abase + ((uint32_t)(wm + (lane & 15)) * NGS + (lane >> 4) * 8) * 2;
            uint32_t aAddr1 = aAddr0 + 16 * NGS * 2;
            uint32_t bAddr  = bbase + ((uint32_t)(wn + (lane & 7)) * NGS + ((lane >> 3) & 1) * 8) * 2;
            #pragma unroll
            for (int ks = 0; ks < 9; ks++) {
                uint32_t koff = (uint32_t)ks * 32;
                uint32_t a0[4], a1[4];
                ldsm_x4(a0, aAddr0 + koff);
                ldsm_x4(a1, aAddr1 + koff);
                uint32_t b[4][2];
                #pragma unroll
                for (int nt = 0; nt < 4; nt++)
                    ldsm_x2(b[nt], bAddr + (uint32_t)nt * 8 * NGS * 2 + koff);
                #pragma unroll
                for (int nt = 0; nt < 4; nt++) {
                    mma_bf16(acc[0][nt], a0, b[nt]);
                    mma_bf16(acc[1][nt], a1, b[nt]);
                }
            }
        }
    }
    __syncthreads();

    // D -> smem (overlays retired A region: 67584B <= 77824B), then coalesced out
    float* sD = (float*)sAh;
    {
        int g = lane >> 2, t2 = (lane & 3) * 2;
        #pragma unroll
        for (int mt = 0; mt < 2; mt++)
            #pragma unroll
            for (int nt = 0; nt < 4; nt++) {
                int r0 = wm + mt * 16 + g, c0 = wn + nt * 8 + t2;
                float2 v0 = make_float2(acc[mt][nt][0], acc[mt][nt][1]);
                float2 v1 = make_float2(acc[mt][nt][2], acc[mt][nt][3]);
                if (RELU) {
                    v0.x = fmaxf(v0.x, 0.f); v0.y = fmaxf(v0.y, 0.f);
                    v1.x = fmaxf(v1.x, 0.f); v1.y = fmaxf(v1.y, 0.f);
                }
                *(float2*)(sD + r0 * SD_STRIDE + c0)       = v0;
                *(float2*)(sD + (r0 + 8) * SD_STRIDE + c0) = v1;
            }
    }
    __syncthreads();
    {
        int row = tid & 127, q = tid >> 7;
        if (m0 + row < NN) {
            const float4* sp = (const float4*)(sD + row * SD_STRIDE + q * 32);
            float* orow = out + (size_t)(m0 + row) * H + q * 32;
            #pragma unroll
            for (int i = 0; i < 8; i++) *(float4*)(orow + i * 4) = sp[i];
        }
    }
}

// ---- initial edge layer: h0 = relu(P[src] + bond @ WbT), stored bf16 hi/lo -
__global__ __launch_bounds__(256) void init_edges(const float* __restrict__ bond,
                                                  const void* __restrict__ src) {
    __shared__ float sWb[BF * H];
    for (int i = threadIdx.x; i < BF * H; i += 256) sWb[i] = g_WbT[i];
    __syncthreads();
    int warp = threadIdx.x >> 5, lane = threadIdx.x & 31;
    for (long e0 = (long)blockIdx.x * 8; e0 < NE; e0 += (long)gridDim.x * 8) {
        long e = e0 + warp;
        int s = ld_idx(src, e);
        int q = lane * 4;
        float4 acc = *(const float4*)(g_P + (size_t)s * H + q);
        const float* br = bond + e * BF;
        #pragma unroll
        for (int k = 0; k < BF; k++) {
            float b = __ldg(br + k);
            float4 w = *(const float4*)(sWb + k * H + q);
            acc.x += b * w.x; acc.y += b * w.y; acc.z += b * w.z; acc.w += b * w.w;
        }
        acc.x = fmaxf(acc.x, 0.f); acc.y = fmaxf(acc.y, 0.f);
        acc.z = fmaxf(acc.z, 0.f); acc.w = fmaxf(acc.w, 0.f);
        __nv_bfloat16 h0,h1,h2,h3,l0,l1,l2,l3;
        bsplit(acc.x,h0,l0); bsplit(acc.y,h1,l1); bsplit(acc.z,h2,l2); bsplit(acc.w,h3,l3);
        size_t off = (size_t)e * H + q;
        *(uint2*)(g_hh + off) = make_uint2(bpack(h0,h1), bpack(h2,h3));
        *(uint2*)(g_hl + off) = make_uint2(bpack(l0,l1), bpack(l2,l3));
    }
}

// ---------------- persistent tensor-core edge GEMM (unchanged from R5) ------
template<int MODE>
__global__ __launch_bounds__(512, 1) void egemm2(
    const __nv_bfloat16* __restrict__ Ah, const __nv_bfloat16* __restrict__ Al,
    const float* __restrict__ Sprev, const float* __restrict__ Yprev,
    const void* __restrict__ srcp, const void* __restrict__ revp,
    const uint4* __restrict__ Bh4, const uint4* __restrict__ Bl4,
    float* __restrict__ Yout, float* __restrict__ Sout,
    const void* __restrict__ dstp)
{
    extern __shared__ __align__(16) char dyn[];
    __nv_bfloat16* sBh = (__nv_bfloat16*)dyn;
    __nv_bfloat16* sBl = sBh + MATB;
    __nv_bfloat16* sSt0 = sBl + MATB;
    __nv_bfloat16* sSt1 = sSt0 + 2 * MATB;

    int tid = threadIdx.x, lane = tid & 31, wid = tid >> 5;

    #pragma unroll
    for (int it = 0; it < 4; it++) {
        int i = tid + it * 512;
        int r = i >> 4, c = i & 15;
        *(uint4*)(sBh + r * SA_STRIDE + c * 8) = __ldg(Bh4 + i);
        *(uint4*)(sBl + r * SA_STRIDE + c * 8) = __ldg(Bl4 + i);
    }

    long tile0 = (long)blockIdx.x * TILES_PER_CTA;

    if (MODE == 0) {
        uint32_t st = smem_u32(sSt0);
        long e0 = tile0 * 128;
        #pragma unroll
        for (int it = 0; it < 4; it++) {
            int i = tid + it * 512;
            int r = i >> 4, c = i & 15;
            uint32_t doff = (uint32_t)(r * SA_STRIDE + c * 8) * 2;
            cp_async16(st + doff, Ah + (size_t)(e0 + r) * H + c * 8);
            cp_async16(st + (uint32_t)MATB * 2 + doff, Al + (size_t)(e0 + r) * H + c * 8);
        }
        cp_commit();
    }

    int wm = (wid >> 2) * 32;
    int wn = (wid & 3) * 32;

    for (int t = 0; t < TILES_PER_CTA; t++) {
        long e0 = (tile0 + t) * 128;
        __nv_bfloat16* sA = (MODE == 0) ? ((t & 1) ? sSt1 : sSt0) : sSt0;
        __nv_bfloat16* sAh = sA;
        __nv_bfloat16* sAl = sA + MATB;

        if (MODE == 0) {
            if (t + 1 < TILES_PER_CTA) {
                __nv_bfloat16* nx = (t & 1) ? sSt0 : sSt1;
                uint32_t st = smem_u32(nx);
                long en = (tile0 + t + 1) * 128;
                #pragma unroll
                for (int it = 0; it < 4; it++) {
                    int i = tid + it * 512;
                    int r = i >> 4, c = i & 15;
                    uint32_t doff = (uint32_t)(r * SA_STRIDE + c * 8) * 2;
                    cp_async16(st + doff, Ah + (size_t)(en + r) * H + c * 8);
                    cp_async16(st + (uint32_t)MATB * 2 + doff, Al + (size_t)(en + r) * H + c * 8);
                }
                cp_commit();
                cp_wait<1>();
            } else {
                cp_wait<0>();
            }
            __syncthreads();
        } else {
            int row = tid >> 2, q = tid & 3;
            long e = e0 + row;
            int  s = ld_idx(srcp, e);
            long r = ld_idx(revp, e);
            const float4* ps = (const float4*)(Sprev + (size_t)s * H + q * 32);
            const float4* py = (const float4*)(Yprev + (size_t)r * H + q * 32);
            uint2* dh = (uint2*)(sAh + row * SA_STRIDE + q * 32);
            uint2* dl = (uint2*)(sAl + row * SA_STRIDE + q * 32);
            #pragma unroll
            for (int i = 0; i < 8; i++) {
                float4 sv = __ldg(ps + i), yv = __ldg(py + i);
                float4 hv;
                hv.x = fmaxf(sv.x - yv.x, 0.f); hv.y = fmaxf(sv.y - yv.y, 0.f);
                hv.z = fmaxf(sv.z - yv.z, 0.f); hv.w = fmaxf(sv.w - yv.w, 0.f);
                __nv_bfloat16 h0,h1,h2,h3,l0,l1,l2,l3;
                bsplit(hv.x,h0,l0); bsplit(hv.y,h1,l1); bsplit(hv.z,h2,l2); bsplit(hv.w,h3,l3);
                dh[i] = make_uint2(bpack(h0,h1), bpack(h2,h3));
                dl[i] = make_uint2(bpack(l0,l1), bpack(l2,l3));
            }
            __syncthreads();
        }

        float acc[2][4][4];
        #pragma unroll
        for (int mt = 0; mt < 2; mt++)
            #pragma unroll
            for (int nt = 0; nt < 4; nt++)
                #pragma unroll
                for (int i = 0; i < 4; i++) acc[mt][nt][i] = 0.f;

        #pragma unroll
        for (int pass = 0; pass < 3; pass++) {
            uint32_t abase = smem_u32(pass == 1 ? sAl : sAh);
            uint32_t bbase = smem_u32(pass == 2 ? sBl : sBh);
            uint32_t aAddr0 = abase + ((uint32_t)(wm + (lane & 15)) * SA_STRIDE + (lane >> 4) * 8) * 2;
            uint32_t aAddr1 = aAddr0 + 16 * SA_STRIDE * 2;
            uint32_t bAddr  = bbase + ((uint32_t)(wn + (lane & 7)) * SA_STRIDE + ((lane >> 3) & 1) * 8) * 2;
            #pragma unroll
            for (int ks = 0; ks < 8; ks++) {
                uint32_t koff = (uint32_t)ks * 32;
                uint32_t a0[4], a1[4];
                ldsm_x4(a0, aAddr0 + koff);
                ldsm_x4(a1, aAddr1 + koff);
                uint32_t b[4][2];
                #pragma unroll
                for (int nt = 0; nt < 4; nt++)
                    ldsm_x2(b[nt], bAddr + (uint32_t)nt * 8 * SA_STRIDE * 2 + koff);
                #pragma unroll
                for (int nt = 0; nt < 4; nt++) {
                    mma_bf16(acc[0][nt], a0, b[nt]);
                    mma_bf16(acc[1][nt], a1, b[nt]);
                }
            }
        }
        __syncthreads();

        float* sD = (float*)sA;
        {
            int g = lane >> 2, t2 = (lane & 3) * 2;
            #pragma unroll
            for (int mt = 0; mt < 2; mt++)
                #pragma unroll
                for (int nt = 0; nt < 4; nt++) {
                    int r0 = wm + mt * 16 + g, c0 = wn + nt * 8 + t2;
                    *(float2*)(sD + r0 * SD_STRIDE + c0)       = make_float2(acc[mt][nt][0], acc[mt][nt][1]);
                    *(float2*)(sD + (r0 + 8) * SD_STRIDE + c0) = make_float2(acc[mt][nt][2], acc[mt][nt][3]);
                }
        }
        __syncthreads();

        {
            int row = tid & 127, q = tid >> 7;
            long e = e0 + row;
            int d = ld_idx(dstp, e);
            const float4* sp = (const float4*)(sD + row * SD_STRIDE + q * 32);
            float* yrow = Yout + (size_t)e * H + q * 32;
            float* srow = Sout + (size_t)d * H + q * 32;
            #pragma unroll
            for (int i = 0; i < 8; i++) {
                float4 v = sp[i];
                *(float4*)(yrow + i * 4) = v;
                red4(srow + i * 4, v);
            }
        }
        __syncthreads();
    }
}

// ------- final combine: scatter relu(S2[src] - Y2[rev]) into S3[dst] --------
__global__ __launch_bounds__(256) void combine2(const float* __restrict__ S,
                                                const float* __restrict__ Yv,
                                                const void* __restrict__ src,
                                                const void* __restrict__ rev,
                                                float* __restrict__ S3,
                                                const void* __restrict__ dst) {
    long g = (long)blockIdx.x * 256 + threadIdx.x;
    long e = g >> 5;
    if (e >= NE) return;
    int q = (int)(g & 31) * 4;
    int s = ld_idx(src, e);
    long r = ld_idx(rev, e);
    int d = ld_idx(dst, e);
    float4 sv = *(const float4*)(S + (size_t)s * H + q);
    float4 yv = *(const float4*)(Yv + (size_t)r * H + q);
    float4 h;
    h.x = fmaxf(sv.x - yv.x, 0.f);
    h.y = fmaxf(sv.y - yv.y, 0.f);
    h.z = fmaxf(sv.z - yv.z, 0.f);
    h.w = fmaxf(sv.w - yv.w, 0.f);
    red4(S3 + (size_t)d * H + q, h);
}

// ---------------- launcher ----------------
extern "C" void kernel_launch(void* const* d_in, const int* in_sizes, int n_in,
                              void* d_out, int out_size) {
    const float* atom = (const float*)d_in[0];
    const float* bond = (const float*)d_in[1];
    const float* Wi   = (const float*)d_in[2];
    const float* Wh   = (const float*)d_in[3];
    const float* Wo   = (const float*)d_in[4];
    const void*  src  = d_in[5];
    const void*  dst  = d_in[6];
    const void*  rev  = d_in[7];
    float* out = (float*)d_out;

    __nv_bfloat16 *hh, *hl, *Bh, *Bl, *W1h, *W1l, *W2h, *W2l, *A1h, *A1l, *A2h, *A2l;
    float *y1, *y2, *P, *S1, *S2, *S3;
    cudaGetSymbolAddress((void**)&hh, g_hh);
    cudaGetSymbolAddress((void**)&hl, g_hl);
    cudaGetSymbolAddress((void**)&Bh, g_Bh);
    cudaGetSymbolAddress((void**)&Bl, g_Bl);
    cudaGetSymbolAddress((void**)&W1h, g_W1h);
    cudaGetSymbolAddress((void**)&W1l, g_W1l);
    cudaGetSymbolAddress((void**)&W2h, g_W2h);
    cudaGetSymbolAddress((void**)&W2l, g_W2l);
    cudaGetSymbolAddress((void**)&A1h, g_A1h);
    cudaGetSymbolAddress((void**)&A1l, g_A1l);
    cudaGetSymbolAddress((void**)&A2h, g_A2h);
    cudaGetSymbolAddress((void**)&A2l, g_A2l);
    cudaGetSymbolAddress((void**)&y1, g_y1);
    cudaGetSymbolAddress((void**)&y2, g_y2);
    cudaGetSymbolAddress((void**)&P,  g_P);
    cudaGetSymbolAddress((void**)&S1, g_S1);
    cudaGetSymbolAddress((void**)&S2, g_S2);
    cudaGetSymbolAddress((void**)&S3, g_S3);

    const int smemG0 = 6 * MATB * 2;   // 208896 B
    const int smemG1 = 4 * MATB * 2;   // 139264 B
    const int smemN  = 4 * NGMAT * 2;  // 155648 B
    cudaFuncSetAttribute(egemm2<0>, cudaFuncAttributeMaxDynamicSharedMemorySize, smemG0);
    cudaFuncSetAttribute(egemm2<1>, cudaFuncAttributeMaxDynamicSharedMemorySize, smemG1);
    cudaFuncSetAttribute(ngemm<144, false>, cudaFuncAttributeMaxDynamicSharedMemorySize, smemN);
    cudaFuncSetAttribute(ngemm<288, true>,  cudaFuncAttributeMaxDynamicSharedMemorySize, smemN);

    // (capture slot = 4th launch -> ngemm<144>)
    prep_w<<<(128 * 288 + 255) / 256, 256>>>(Wi, Wh, Wo);
    cvt1<<<(int)(((long)NROWS_PAD * 144 + 511) / 512), 512>>>(atom);
    zero3<<<3 * NN * H / 4 / 256, 256>>>((float4*)S1, (float4*)S2, (float4*)S3);

    // P = atom @ Wa^T  (mma)
    ngemm<144, false><<<NGRID, 512, smemN>>>(A1h, A1l, W1h, W1l, P);

    detect_idx<<<1, 256>>>((const unsigned int*)src);
    // h0 (bf16 hi/lo) = relu(P[src] + bond @ Wb^T)
    init_edges<<<2048, 256>>>(bond, src);

    // iter 1: Y1 = h0 @ Wh^T, scatter S1
    egemm2<0><<<EGRID, 512, smemG0>>>(hh, hl, nullptr, nullptr, nullptr, nullptr,
                                      (const uint4*)Bh, (const uint4*)Bl, y1, S1, dst);
    // iter 2: rows = relu(S1[src] - Y1[rev]); Y2, scatter S2
    egemm2<1><<<EGRID, 512, smemG1>>>(nullptr, nullptr, S1, y1, src, rev,
                                      (const uint4*)Bh, (const uint4*)Bl, y2, S2, dst);
    // scatter relu(S2[src] - Y2[rev]) into S3
    combine2<<<NE * 32 / 256, 256>>>(S2, y2, src, rev, S3, dst);

    // out = relu([atom | S3] @ Wo^T)  (mma)
    cvt2<<<(int)(((long)NROWS_PAD * 288 + 511) / 512), 512>>>(atom, S3);
    ngemm<288, true><<<NGRID, 512, smemN>>>(A2h, A2l, W2h, W2l, out);
}